// round 16
// baseline (speedup 1.0000x reference)
#include <cuda_runtime.h>
#include <cuda_fp16.h>
#include <cstdint>

#define N_ROWS  65536
#define DIM     256
#define N_CODES 2048
#define THRESH  0.05f
#define V1TOL   0.04f
#define LCAP    (2 * N_ROWS)

// ---------------- device scratch ----------------
__device__ float              g_cbsq[N_CODES];
__device__ int                g_best[N_ROWS];
__device__ float              g_bestkey[N_ROWS];
__device__ unsigned int       g_hist[N_CODES];
__device__ double             g_closs;
__device__ int                g_count;
__device__ int                g_bad;
__device__ int                g_list[LCAP];
__device__ unsigned long long g_packed[N_ROWS];
// codebook packed in mma-B-fragment order:
// block (cb8, kstep): 32 lanes x 16B = [hi_b0 | hi_b1 | lo_b0 | lo_b1]
__device__ __align__(16) uint4 g_cbp[256 * 16 * 32];   // 2 MB

// ---------------- PTX helpers ----------------
#define MMAF16(C, A, b0, b1) \
    asm volatile("mma.sync.aligned.m16n8k16.row.col.f32.f16.f16.f32 " \
        "{%0,%1,%2,%3}, {%4,%5,%6,%7}, {%8,%9}, {%0,%1,%2,%3};" \
        : "+f"((C)[0]), "+f"((C)[1]), "+f"((C)[2]), "+f"((C)[3]) \
        : "r"((A)[0]), "r"((A)[1]), "r"((A)[2]), "r"((A)[3]), "r"(b0), "r"(b1))
#define LDSM4(R, addr) \
    asm volatile("ldmatrix.sync.aligned.m8n8.x4.shared.b16 {%0,%1,%2,%3}, [%4];" \
        : "=r"((R)[0]), "=r"((R)[1]), "=r"((R)[2]), "=r"((R)[3]) : "r"(addr))
__device__ __forceinline__ uint32_t smem_u32(const void* p) {
    uint32_t a;
    asm("{ .reg .u64 t; cvta.to.shared.u64 t, %1; cvt.u32.u64 %0, t; }" : "=r"(a) : "l"(p));
    return a;
}

// ---------------- SMEM layout (bytes), M=64 CTA ----------------
#define A_PITCH    528
#define AH_OFF     0             // 64*528 = 33792
#define MERGE_OFF  33792
#define SMEM_TOTAL 36864
#define NT         256           // 8 warps: warp_m = wid&1, warp_n = wid>>1

// ---------------- fused prep: zero counters + cbsq + fragment pack ----------------
__global__ void prep_kernel(const float* __restrict__ cb) {
    int bid = blockIdx.x;      // 256 blocks
    int tid = threadIdx.x;

    int gt = bid * 256 + tid;
    if (gt < N_CODES) g_hist[gt] = 0u;
    if (gt == 0) { g_closs = 0.0; g_count = 0; g_bad = 0; }

    {
        int code = bid * 8 + (tid >> 5);
        int lane = tid & 31;
        const float4* r = (const float4*)(cb + (size_t)code * DIM);
        float s = 0.f;
#pragma unroll
        for (int j = 0; j < 2; j++) {
            float4 v = r[lane + 32 * j];
            s += v.x * v.x + v.y * v.y + v.z * v.z + v.w * v.w;
        }
#pragma unroll
        for (int off = 16; off; off >>= 1) s += __shfl_xor_sync(0xffffffffu, s, off);
        if (lane == 0) g_cbsq[code] = s;
    }

    if (tid < 128) {
        int i = bid * 128 + tid;
        int c = i >> 4, kstep = i & 15;
        int cb8 = c >> 3, gg = c & 7;
        const float4* src = (const float4*)(cb + (size_t)c * DIM + kstep * 16);
        float xs[16];
#pragma unroll
        for (int q = 0; q < 4; q++) {
            float4 v = src[q];
            xs[q * 4 + 0] = v.x; xs[q * 4 + 1] = v.y; xs[q * 4 + 2] = v.z; xs[q * 4 + 3] = v.w;
        }
        unsigned short hi[16], lo[16];
#pragma unroll
        for (int q = 0; q < 16; q++) {
            __half h = __float2half_rn(xs[q]);
            __half l = __float2half_rn(xs[q] - __half2float(h));
            hi[q] = __half_as_ushort(h);
            lo[q] = __half_as_ushort(l);
        }
        uint4* dst = g_cbp + ((size_t)(cb8 * 16 + kstep) * 32 + gg * 4);
#pragma unroll
        for (int tig = 0; tig < 4; tig++) {
            uint4 o;
            o.x = hi[tig * 2]     | ((unsigned)hi[tig * 2 + 1] << 16);
            o.y = hi[8 + tig * 2] | ((unsigned)hi[8 + tig * 2 + 1] << 16);
            o.z = lo[tig * 2]     | ((unsigned)lo[tig * 2 + 1] << 16);
            o.w = lo[8 + tig * 2] | ((unsigned)lo[8 + tig * 2 + 1] << 16);
            dst[tig] = o;
        }
    }
}

__device__ __forceinline__ void upd(float& bk, float& bk2, int& bi, float k, int c) {
    if (k < bk) { bk2 = bk; bk = k; bi = c; }
    else if (k < bk2) bk2 = k;
}

// ---------------- fused HMMA GEMM + argmin (ldmatrix A, B LDG + reg prefetch) ----------------
__global__ __launch_bounds__(NT, 2) void vq_mma_kernel(const float* __restrict__ z) {
    extern __shared__ char smem[];
    const uint32_t sbase = smem_u32(smem);
    const int tid = threadIdx.x;
    const int lane = tid & 31, wid = tid >> 5;
    const int g   = lane >> 2;
    const int tig = lane & 3;
    const int warp_m = wid & 1;
    const int warp_n = wid >> 1;
    const int rowBase = blockIdx.x * 64;

    const float* zrow = z + (size_t)rowBase * DIM;
#pragma unroll
    for (int j = 0; j < 8; j++) {
        int i = tid + j * NT;
        int row = i >> 5, c = i & 31;
        const float4* p = (const float4*)(zrow + (size_t)row * DIM + c * 8);
        float4 v0 = p[0], v1 = p[1];
        float xs[8] = {v0.x, v0.y, v0.z, v0.w, v1.x, v1.y, v1.z, v1.w};
        unsigned short hs[8];
#pragma unroll
        for (int q = 0; q < 8; q++) hs[q] = __half_as_ushort(__float2half_rn(xs[q]));
        uint4 uh;
        uh.x = hs[0] | ((unsigned)hs[1] << 16); uh.y = hs[2] | ((unsigned)hs[3] << 16);
        uh.z = hs[4] | ((unsigned)hs[5] << 16); uh.w = hs[6] | ((unsigned)hs[7] << 16);
        *(uint4*)(smem + AH_OFF + row * A_PITCH + c * 16) = uh;
    }
    __syncthreads();

    float bk[4], bk2[4]; int bi[4];
#pragma unroll
    for (int r = 0; r < 4; r++) { bk[r] = 1e30f; bk2[r] = 1e30f; bi[r] = 0; }

    const int r16 = (lane & 7) + ((lane >> 3) & 1) * 8;
    const uint32_t a_ldsm = sbase + AH_OFF
        + (uint32_t)((warp_m * 32 + r16) * A_PITCH + (lane >> 4) * 16);

    for (int nt = 0; nt < 8; nt++) {
#pragma unroll
        for (int half = 0; half < 2; half++) {
            float acc[2][4][4];
#pragma unroll
            for (int a = 0; a < 2; a++)
#pragma unroll
                for (int b = 0; b < 4; b++)
#pragma unroll
                    for (int c = 0; c < 4; c++) acc[a][b][c] = 0.f;

            const uint4* bbase = g_cbp
                + ((size_t)(nt * 32 + warp_n * 8 + half * 4) * 16) * 32 + lane;

            uint4 vb[4];
#pragma unroll
            for (int j = 0; j < 4; j++) vb[j] = __ldg(bbase + (size_t)j * 16 * 32);

#pragma unroll 4
            for (int kstep = 0; kstep < 16; kstep++) {
                uint4 vn[4];
                if (kstep < 15) {
#pragma unroll
                    for (int j = 0; j < 4; j++)
                        vn[j] = __ldg(bbase + ((size_t)j * 16 + kstep + 1) * 32);
                }
                uint32_t ah[2][4];
                LDSM4(ah[0], a_ldsm + kstep * 32);
                LDSM4(ah[1], a_ldsm + 16 * A_PITCH + kstep * 32);
#pragma unroll
                for (int j = 0; j < 4; j++) {
                    MMAF16(acc[0][j], ah[0], vb[j].x, vb[j].y);
                    MMAF16(acc[0][j], ah[0], vb[j].z, vb[j].w);
                    MMAF16(acc[1][j], ah[1], vb[j].x, vb[j].y);
                    MMAF16(acc[1][j], ah[1], vb[j].z, vb[j].w);
                }
                if (kstep < 15) {
#pragma unroll
                    for (int j = 0; j < 4; j++) vb[j] = vn[j];
                }
            }

#pragma unroll
            for (int mf = 0; mf < 2; mf++)
#pragma unroll
                for (int j = 0; j < 4; j++) {
                    int code0 = nt * 256 + warp_n * 64 + half * 32 + j * 8 + tig * 2;
                    float2 cq = __ldg((const float2*)(g_cbsq + code0));
                    float k00 = fmaf(-2.f, acc[mf][j][0], cq.x);
                    float k01 = fmaf(-2.f, acc[mf][j][1], cq.y);
                    float k10 = fmaf(-2.f, acc[mf][j][2], cq.x);
                    float k11 = fmaf(-2.f, acc[mf][j][3], cq.y);
                    upd(bk[mf * 2],     bk2[mf * 2],     bi[mf * 2],     k00, code0);
                    upd(bk[mf * 2],     bk2[mf * 2],     bi[mf * 2],     k01, code0 + 1);
                    upd(bk[mf * 2 + 1], bk2[mf * 2 + 1], bi[mf * 2 + 1], k10, code0);
                    upd(bk[mf * 2 + 1], bk2[mf * 2 + 1], bi[mf * 2 + 1], k11, code0 + 1);
                }
        }
    }

    float* mK  = (float*)(smem + MERGE_OFF);
    float* mK2 = mK + 256;
    int*   mI  = (int*)(mK + 512);
#pragma unroll
    for (int r = 0; r < 4; r++) {
#pragma unroll
        for (int off = 1; off <= 2; off <<= 1) {
            float ok  = __shfl_xor_sync(0xffffffffu, bk[r], off);
            float ok2 = __shfl_xor_sync(0xffffffffu, bk2[r], off);
            int   oi  = __shfl_xor_sync(0xffffffffu, bi[r], off);
            if (ok < bk[r]) { bk2[r] = fminf(bk[r], ok2); bk[r] = ok; bi[r] = oi; }
            else            { bk2[r] = fminf(bk2[r], ok); }
        }
        if (tig == 0) {
            int rin = warp_m * 32 + (r >> 1) * 16 + (r & 1) * 8 + g;
            mK[warp_n * 64 + rin]  = bk[r];
            mK2[warp_n * 64 + rin] = bk2[r];
            mI[warp_n * 64 + rin]  = bi[r];
        }
    }
    __syncthreads();
    if (tid < 64) {
        float B1 = 1e30f, B2 = 1e30f; int BI = 0;
#pragma unroll
        for (int n = 0; n < 4; n++) {
            float k1 = mK[n * 64 + tid], k2 = mK2[n * 64 + tid];
            int   ii = mI[n * 64 + tid];
            if (k1 < B1) { B2 = fminf(B1, k2); B1 = k1; BI = ii; }
            else         { B2 = fminf(B2, k1); }
        }
        int row = rowBase + tid;
        g_best[row] = BI;
        g_bestkey[row] = B1;
        if (B2 - B1 < THRESH) {
            g_packed[row] = ~0ull;
            int pos = atomicAdd(&g_count, 1);
            if (pos < LCAP) g_list[pos] = row;
        }
    }
}

// ---------------- verify1: per-row key consistency -> repair list ----------------
__global__ void verify1_kernel(const float* __restrict__ z, const float* __restrict__ cb) {
    int warp = threadIdx.x >> 5, lane = threadIdx.x & 31;
    int row = blockIdx.x * 8 + warp;
    int best = g_best[row];
    const float4* c4 = (const float4*)(cb + (size_t)best * DIM);
    const float4* z4 = (const float4*)(z + (size_t)row * DIM);
    float d = 0.f;
#pragma unroll
    for (int j = 0; j < 2; j++) {
        float4 a = z4[lane + 32 * j], b = c4[lane + 32 * j];
        d = fmaf(a.x, b.x, d); d = fmaf(a.y, b.y, d);
        d = fmaf(a.z, b.z, d); d = fmaf(a.w, b.w, d);
    }
#pragma unroll
    for (int off = 16; off; off >>= 1) d += __shfl_xor_sync(0xffffffffu, d, off);
    if (lane == 0) {
        float key = fmaf(-2.f, d, g_cbsq[best]);
        if (fabsf(key - g_bestkey[row]) > V1TOL) {
            g_packed[row] = ~0ull;
            int pos = atomicAdd(&g_count, 1);
            if (pos < LCAP) g_list[pos] = row;
        }
    }
}

// ---------------- exact rescore: one block per listed row, 8 shfl-chains in flight ----------------
__device__ __forceinline__ unsigned long long pack_key(float k, int code) {
    unsigned u = __float_as_uint(k);
    u = (u & 0x80000000u) ? ~u : (u | 0x80000000u);
    return ((unsigned long long)u << 32) | (unsigned)code;
}

__global__ void rescore_kernel(const float* __restrict__ z, const float* __restrict__ cb) {
    __shared__ float zr[DIM];
    int count = g_count; if (count > LCAP) count = LCAP;
    int tid = threadIdx.x, wid = tid >> 5, lane = tid & 31;

    for (int li = blockIdx.x; li < count; li += gridDim.x) {
        int row = g_list[li];
        __syncthreads();
        for (int i = tid; i < DIM; i += 256) zr[i] = z[(size_t)row * DIM + i];
        __syncthreads();

        const float4* zz = (const float4*)(zr + lane * 8);
        float4 a0 = zz[0], a1 = zz[1];

        unsigned long long bestp = ~0ull;
        // warp covers codes [wid*256, wid*256+256), 8 independent shfl chains in flight
#pragma unroll
        for (int jo = 0; jo < 256; jo += 8) {
            float dd[8];
#pragma unroll
            for (int u = 0; u < 8; u++) {
                int code = wid * 256 + jo + u;
                const float4* c4 = (const float4*)(cb + (size_t)code * DIM + lane * 8);
                float4 b0 = __ldg(c4), b1 = __ldg(c4 + 1);
                float d0 = a0.x * b0.x + a0.y * b0.y;
                float d1 = a0.z * b0.z + a0.w * b0.w;
                d0 += a1.x * b1.x + a1.y * b1.y;
                d1 += a1.z * b1.z + a1.w * b1.w;
                dd[u] = d0 + d1;
            }
#pragma unroll
            for (int off = 16; off; off >>= 1)
#pragma unroll
                for (int u = 0; u < 8; u++)
                    dd[u] += __shfl_xor_sync(0xffffffffu, dd[u], off);
#pragma unroll
            for (int u = 0; u < 8; u++) {
                int code = wid * 256 + jo + u;
                float key = fmaf(-2.f, dd[u], __ldg(g_cbsq + code));
                unsigned long long p = pack_key(key, code);
                if (p < bestp) bestp = p;
            }
        }
        if (lane == 0) atomicMin(&g_packed[row], bestp);
    }
}

__global__ void fixup_kernel() {
    int count = g_count; if (count > LCAP) count = LCAP;
    for (int i = blockIdx.x * 256 + threadIdx.x; i < count; i += gridDim.x * 256) {
        int row = g_list[i];
        g_best[row] = (int)(g_packed[row] & 0xffffffffull);
    }
}

// ---------------- verify2: sampled exact argmin on repaired state (sets g_bad) ----------------
__global__ void verify2_kernel(const float* __restrict__ z, const float* __restrict__ cb) {
    __shared__ float zr[256];
    __shared__ float smin[256];
    __shared__ float sbk;
    int s = blockIdx.x, t = threadIdx.x;
    int row = s * 1024 + ((s * 37) & 127);
    int best = g_best[row];
    zr[t] = z[(size_t)row * DIM + t];
    if (t == 0) sbk = 1e30f;
    __syncthreads();
    const float4* z4 = (const float4*)zr;
    float m = 1e30f;
#pragma unroll 2
    for (int j = 0; j < 8; j++) {
        int code = t + j * 256;
        const float4* c4 = (const float4*)(cb + (size_t)code * DIM);
        float d = 0.f;
#pragma unroll 8
        for (int q = 0; q < 64; q++) {
            float4 a = z4[q], b = c4[q];
            d = fmaf(a.x, b.x, d); d = fmaf(a.y, b.y, d);
            d = fmaf(a.z, b.z, d); d = fmaf(a.w, b.w, d);
        }
        float key = fmaf(-2.f, d, g_cbsq[code]);
        m = fminf(m, key);
        if (code == best) sbk = key;
    }
    smin[t] = m;
    __syncthreads();
    for (int w = 128; w; w >>= 1) {
        if (t < w) smin[t] = fminf(smin[t], smin[t + w]);
        __syncthreads();
    }
    if (t == 0 && sbk > smin[0] + 0.04f) g_bad = 1;
}

// ---------------- fallback: exact FFMA argmin (catastrophe only) ----------------
#define FTM 64
#define FTN 64
#define FKC 32
#define FB_SMEM ((DIM*FTM + FTN*(FKC+1)) * (int)sizeof(float))

__global__ __launch_bounds__(256) void fallback_kernel(
    const float* __restrict__ z, const float* __restrict__ cb) {
    if (g_bad == 0) return;
    extern __shared__ float fsm[];
    float (*sZ)[FTM]      = (float (*)[FTM])fsm;
    float (*sC)[FKC + 1]  = (float (*)[FKC + 1])(fsm + DIM * FTM);

    const int tid = threadIdx.x;
    const int rowBase = blockIdx.x * FTM;

    for (int i = tid; i < FTM * DIM; i += 256) {
        int m = i >> 8, k = i & 255;
        sZ[k][m] = z[(size_t)(rowBase + m) * DIM + k];
    }

    const int cg = tid & 15;
    const int rg = tid >> 4;

    float bestKey[4] = {1e30f, 1e30f, 1e30f, 1e30f};
    int   bestIdx[4] = {0, 0, 0, 0};

    for (int ct = 0; ct < N_CODES; ct += FTN) {
        float acc[4][4];
#pragma unroll
        for (int a = 0; a < 4; a++)
#pragma unroll
            for (int b = 0; b < 4; b++) acc[a][b] = 0.f;

        for (int kc = 0; kc < DIM; kc += FKC) {
            __syncthreads();
            {
                int c = tid >> 5, kk = tid & 31;
#pragma unroll
                for (int j = 0; j < 8; j++)
                    sC[c + 8 * j][kk] = cb[(size_t)(ct + c + 8 * j) * DIM + kc + kk];
            }
            __syncthreads();

#pragma unroll 8
            for (int k = 0; k < FKC; k++) {
                float4 zv = *(const float4*)(&sZ[kc + k][rg * 4]);
                float c0 = sC[cg * 4 + 0][k];
                float c1 = sC[cg * 4 + 1][k];
                float c2 = sC[cg * 4 + 2][k];
                float c3 = sC[cg * 4 + 3][k];
                acc[0][0] += zv.x * c0; acc[0][1] += zv.x * c1; acc[0][2] += zv.x * c2; acc[0][3] += zv.x * c3;
                acc[1][0] += zv.y * c0; acc[1][1] += zv.y * c1; acc[1][2] += zv.y * c2; acc[1][3] += zv.y * c3;
                acc[2][0] += zv.z * c0; acc[2][1] += zv.z * c1; acc[2][2] += zv.z * c2; acc[2][3] += zv.z * c3;
                acc[3][0] += zv.w * c0; acc[3][1] += zv.w * c1; acc[3][2] += zv.w * c2; acc[3][3] += zv.w * c3;
            }
        }

#pragma unroll
        for (int ci = 0; ci < 4; ci++) {
            int code = ct + cg * 4 + ci;
            float csq = g_cbsq[code];
#pragma unroll
            for (int ri = 0; ri < 4; ri++) {
                float key = csq - 2.f * acc[ri][ci];
                if (key < bestKey[ri]) { bestKey[ri] = key; bestIdx[ri] = code; }
            }
        }
    }

#pragma unroll
    for (int ri = 0; ri < 4; ri++) {
        float k = bestKey[ri];
        int ix = bestIdx[ri];
#pragma unroll
        for (int off = 8; off; off >>= 1) {
            float k2 = __shfl_xor_sync(0xffffffffu, k, off);
            int   i2 = __shfl_xor_sync(0xffffffffu, ix, off);
            if (k2 < k || (k2 == k && i2 < ix)) { k = k2; ix = i2; }
        }
        if (cg == 0) g_best[rowBase + rg * 4 + ri] = ix;
    }
}

// ---------------- gather + losses ----------------
__global__ void gather_kernel(const float* __restrict__ z, const float* __restrict__ cb,
                              float* __restrict__ out_zq, float* __restrict__ out_idx,
                              int write_idx) {
    __shared__ float warp_s[8];
    int warp = threadIdx.x >> 5, lane = threadIdx.x & 31;
    int row = blockIdx.x * 8 + warp;
    int idx = g_best[row];

    const float4* src = (const float4*)(cb + (size_t)idx * DIM);
    const float4* zr  = (const float4*)(z + (size_t)row * DIM);
    float4*       dst = (float4*)(out_zq + (size_t)row * DIM);

    float s = 0.f;
#pragma unroll
    for (int j = 0; j < 2; j++) {
        int e = lane + 32 * j;
        float4 c = src[e];
        float4 v = zr[e];
        dst[e] = c;
        float dx = c.x - v.x, dy = c.y - v.y, dz = c.z - v.z, dw = c.w - v.w;
        s += dx * dx + dy * dy + dz * dz + dw * dw;
    }
#pragma unroll
    for (int off = 16; off; off >>= 1) s += __shfl_xor_sync(0xffffffffu, s, off);
    if (lane == 0) {
        warp_s[warp] = s;
        atomicAdd(&g_hist[idx], 1u);
        if (write_idx) out_idx[row] = (float)idx;
    }
    __syncthreads();
    if (threadIdx.x == 0) {
        float tt = 0.f;
#pragma unroll
        for (int w = 0; w < 8; w++) tt += warp_s[w];
        atomicAdd(&g_closs, (double)tt);
    }
}

__global__ void finalize_kernel(float* __restrict__ out_losses, int write_losses) {
    __shared__ double sh[256];
    int t = threadIdx.x;
    double e = 0.0;
    for (int c = t; c < N_CODES; c += 256) {
        float p = (float)g_hist[c] / (float)N_ROWS;
        e += (double)(p * logf(p + 1e-10f));
    }
    sh[t] = e;
    __syncthreads();
    for (int s = 128; s; s >>= 1) {
        if (t < s) sh[t] += sh[t + s];
        __syncthreads();
    }
    if (t == 0 && write_losses) {
        double entropy = -sh[0];
        float closs = (float)(g_closs / (double)((long long)N_ROWS * DIM));
        out_losses[0] = closs;
        out_losses[1] = logf((float)N_CODES) - (float)entropy;
    }
}

extern "C" void kernel_launch(void* const* d_in, const int* in_sizes, int n_in,
                              void* d_out, int out_size) {
    const float* z  = (const float*)d_in[0];
    const float* cb = (const float*)d_in[1];
    float* out = (float*)d_out;

    const long long ZQ = (long long)N_ROWS * DIM;
    int write_idx    = (long long)out_size >= ZQ + N_ROWS;
    int write_losses = (long long)out_size >= ZQ + N_ROWS + 2;

    cudaFuncSetAttribute(vq_mma_kernel,
                         cudaFuncAttributeMaxDynamicSharedMemorySize, SMEM_TOTAL);
    cudaFuncSetAttribute(fallback_kernel,
                         cudaFuncAttributeMaxDynamicSharedMemorySize, FB_SMEM);

    prep_kernel<<<N_CODES / 8, 256>>>(cb);
    vq_mma_kernel<<<N_ROWS / 64, NT, SMEM_TOTAL>>>(z);
    verify1_kernel<<<N_ROWS / 8, 256>>>(z, cb);
    rescore_kernel<<<2048, 256>>>(z, cb);
    fixup_kernel<<<64, 256>>>();
    verify2_kernel<<<64, 256>>>(z, cb);
    fallback_kernel<<<N_ROWS / FTM, 256, FB_SMEM>>>(z, cb);
    gather_kernel<<<N_ROWS / 8, 256>>>(z, cb, out, out + ZQ, write_idx);
    finalize_kernel<<<1, 256>>>(out + ZQ + N_ROWS, write_losses);
}

// round 17
// speedup vs baseline: 1.0560x; 1.0560x over previous
#include <cuda_runtime.h>
#include <cuda_fp16.h>
#include <cstdint>

#define N_ROWS  65536
#define DIM     256
#define N_CODES 2048
#define THRESH  0.05f
#define V1TOL   0.04f
#define LCAP    (2 * N_ROWS)

// ---------------- device scratch ----------------
__device__ float              g_cbsq[N_CODES];
__device__ int                g_best[N_ROWS];
__device__ float              g_bestkey[N_ROWS];
__device__ unsigned int       g_hist[N_CODES];
__device__ double             g_closs;
__device__ int                g_count;
__device__ int                g_bad;
__device__ int                g_list[LCAP];
__device__ unsigned long long g_packed[N_ROWS];
// codebook packed in mma-B-fragment order:
// block (cb8, kstep): 32 lanes x 16B = [hi_b0 | hi_b1 | lo_b0 | lo_b1]
__device__ __align__(16) uint4 g_cbp[256 * 16 * 32];   // 2 MB

// ---------------- PTX helpers ----------------
#define MMAF16(C, A, b0, b1) \
    asm volatile("mma.sync.aligned.m16n8k16.row.col.f32.f16.f16.f32 " \
        "{%0,%1,%2,%3}, {%4,%5,%6,%7}, {%8,%9}, {%0,%1,%2,%3};" \
        : "+f"((C)[0]), "+f"((C)[1]), "+f"((C)[2]), "+f"((C)[3]) \
        : "r"((A)[0]), "r"((A)[1]), "r"((A)[2]), "r"((A)[3]), "r"(b0), "r"(b1))
#define LDSM4(R, addr) \
    asm volatile("ldmatrix.sync.aligned.m8n8.x4.shared.b16 {%0,%1,%2,%3}, [%4];" \
        : "=r"((R)[0]), "=r"((R)[1]), "=r"((R)[2]), "=r"((R)[3]) : "r"(addr))
__device__ __forceinline__ uint32_t smem_u32(const void* p) {
    uint32_t a;
    asm("{ .reg .u64 t; cvta.to.shared.u64 t, %1; cvt.u32.u64 %0, t; }" : "=r"(a) : "l"(p));
    return a;
}

// ---------------- SMEM layout (bytes), M=64 CTA ----------------
#define A_PITCH    528
#define AH_OFF     0             // 64*528 = 33792
#define MERGE_OFF  33792
#define SMEM_TOTAL 36864
#define NT         256           // 8 warps: warp_m = wid&1, warp_n = wid>>1

// ---------------- fused prep: zero counters + cbsq + fragment pack ----------------
__global__ void prep_kernel(const float* __restrict__ cb) {
    int bid = blockIdx.x;      // 256 blocks
    int tid = threadIdx.x;

    int gt = bid * 256 + tid;
    if (gt < N_CODES) g_hist[gt] = 0u;
    if (gt == 0) { g_closs = 0.0; g_count = 0; g_bad = 0; }

    {
        int code = bid * 8 + (tid >> 5);
        int lane = tid & 31;
        const float4* r = (const float4*)(cb + (size_t)code * DIM);
        float s = 0.f;
#pragma unroll
        for (int j = 0; j < 2; j++) {
            float4 v = r[lane + 32 * j];
            s += v.x * v.x + v.y * v.y + v.z * v.z + v.w * v.w;
        }
#pragma unroll
        for (int off = 16; off; off >>= 1) s += __shfl_xor_sync(0xffffffffu, s, off);
        if (lane == 0) g_cbsq[code] = s;
    }

    if (tid < 128) {
        int i = bid * 128 + tid;
        int c = i >> 4, kstep = i & 15;
        int cb8 = c >> 3, gg = c & 7;
        const float4* src = (const float4*)(cb + (size_t)c * DIM + kstep * 16);
        float xs[16];
#pragma unroll
        for (int q = 0; q < 4; q++) {
            float4 v = src[q];
            xs[q * 4 + 0] = v.x; xs[q * 4 + 1] = v.y; xs[q * 4 + 2] = v.z; xs[q * 4 + 3] = v.w;
        }
        unsigned short hi[16], lo[16];
#pragma unroll
        for (int q = 0; q < 16; q++) {
            __half h = __float2half_rn(xs[q]);
            __half l = __float2half_rn(xs[q] - __half2float(h));
            hi[q] = __half_as_ushort(h);
            lo[q] = __half_as_ushort(l);
        }
        uint4* dst = g_cbp + ((size_t)(cb8 * 16 + kstep) * 32 + gg * 4);
#pragma unroll
        for (int tig = 0; tig < 4; tig++) {
            uint4 o;
            o.x = hi[tig * 2]     | ((unsigned)hi[tig * 2 + 1] << 16);
            o.y = hi[8 + tig * 2] | ((unsigned)hi[8 + tig * 2 + 1] << 16);
            o.z = lo[tig * 2]     | ((unsigned)lo[tig * 2 + 1] << 16);
            o.w = lo[8 + tig * 2] | ((unsigned)lo[8 + tig * 2 + 1] << 16);
            dst[tig] = o;
        }
    }
}

__device__ __forceinline__ void upd(float& bk, float& bk2, int& bi, float k, int c) {
    if (k < bk) { bk2 = bk; bk = k; bi = c; }
    else if (k < bk2) bk2 = k;
}

// ---------------- fused HMMA GEMM + argmin (ldmatrix A, B LDG + reg prefetch) ----------------
__global__ __launch_bounds__(NT, 2) void vq_mma_kernel(const float* __restrict__ z) {
    extern __shared__ char smem[];
    const uint32_t sbase = smem_u32(smem);
    const int tid = threadIdx.x;
    const int lane = tid & 31, wid = tid >> 5;
    const int g   = lane >> 2;
    const int tig = lane & 3;
    const int warp_m = wid & 1;
    const int warp_n = wid >> 1;
    const int rowBase = blockIdx.x * 64;

    const float* zrow = z + (size_t)rowBase * DIM;
#pragma unroll
    for (int j = 0; j < 8; j++) {
        int i = tid + j * NT;
        int row = i >> 5, c = i & 31;
        const float4* p = (const float4*)(zrow + (size_t)row * DIM + c * 8);
        float4 v0 = p[0], v1 = p[1];
        float xs[8] = {v0.x, v0.y, v0.z, v0.w, v1.x, v1.y, v1.z, v1.w};
        unsigned short hs[8];
#pragma unroll
        for (int q = 0; q < 8; q++) hs[q] = __half_as_ushort(__float2half_rn(xs[q]));
        uint4 uh;
        uh.x = hs[0] | ((unsigned)hs[1] << 16); uh.y = hs[2] | ((unsigned)hs[3] << 16);
        uh.z = hs[4] | ((unsigned)hs[5] << 16); uh.w = hs[6] | ((unsigned)hs[7] << 16);
        *(uint4*)(smem + AH_OFF + row * A_PITCH + c * 16) = uh;
    }
    __syncthreads();

    float bk[4], bk2[4]; int bi[4];
#pragma unroll
    for (int r = 0; r < 4; r++) { bk[r] = 1e30f; bk2[r] = 1e30f; bi[r] = 0; }

    const int r16 = (lane & 7) + ((lane >> 3) & 1) * 8;
    const uint32_t a_ldsm = sbase + AH_OFF
        + (uint32_t)((warp_m * 32 + r16) * A_PITCH + (lane >> 4) * 16);

    for (int nt = 0; nt < 8; nt++) {
#pragma unroll
        for (int half = 0; half < 2; half++) {
            float acc[2][4][4];
#pragma unroll
            for (int a = 0; a < 2; a++)
#pragma unroll
                for (int b = 0; b < 4; b++)
#pragma unroll
                    for (int c = 0; c < 4; c++) acc[a][b][c] = 0.f;

            const uint4* bbase = g_cbp
                + ((size_t)(nt * 32 + warp_n * 8 + half * 4) * 16) * 32 + lane;

            uint4 vb[4];
#pragma unroll
            for (int j = 0; j < 4; j++) vb[j] = __ldg(bbase + (size_t)j * 16 * 32);

#pragma unroll 8
            for (int kstep = 0; kstep < 16; kstep++) {
                uint4 vn[4];
                if (kstep < 15) {
#pragma unroll
                    for (int j = 0; j < 4; j++)
                        vn[j] = __ldg(bbase + ((size_t)j * 16 + kstep + 1) * 32);
                }
                uint32_t ah[2][4];
                LDSM4(ah[0], a_ldsm + kstep * 32);
                LDSM4(ah[1], a_ldsm + 16 * A_PITCH + kstep * 32);
#pragma unroll
                for (int j = 0; j < 4; j++) {
                    MMAF16(acc[0][j], ah[0], vb[j].x, vb[j].y);
                    MMAF16(acc[0][j], ah[0], vb[j].z, vb[j].w);
                    MMAF16(acc[1][j], ah[1], vb[j].x, vb[j].y);
                    MMAF16(acc[1][j], ah[1], vb[j].z, vb[j].w);
                }
                if (kstep < 15) {
#pragma unroll
                    for (int j = 0; j < 4; j++) vb[j] = vn[j];
                }
            }

#pragma unroll
            for (int mf = 0; mf < 2; mf++)
#pragma unroll
                for (int j = 0; j < 4; j++) {
                    int code0 = nt * 256 + warp_n * 64 + half * 32 + j * 8 + tig * 2;
                    float2 cq = __ldg((const float2*)(g_cbsq + code0));
                    float k00 = fmaf(-2.f, acc[mf][j][0], cq.x);
                    float k01 = fmaf(-2.f, acc[mf][j][1], cq.y);
                    float k10 = fmaf(-2.f, acc[mf][j][2], cq.x);
                    float k11 = fmaf(-2.f, acc[mf][j][3], cq.y);
                    upd(bk[mf * 2],     bk2[mf * 2],     bi[mf * 2],     k00, code0);
                    upd(bk[mf * 2],     bk2[mf * 2],     bi[mf * 2],     k01, code0 + 1);
                    upd(bk[mf * 2 + 1], bk2[mf * 2 + 1], bi[mf * 2 + 1], k10, code0);
                    upd(bk[mf * 2 + 1], bk2[mf * 2 + 1], bi[mf * 2 + 1], k11, code0 + 1);
                }
        }
    }

    float* mK  = (float*)(smem + MERGE_OFF);
    float* mK2 = mK + 256;
    int*   mI  = (int*)(mK + 512);
#pragma unroll
    for (int r = 0; r < 4; r++) {
#pragma unroll
        for (int off = 1; off <= 2; off <<= 1) {
            float ok  = __shfl_xor_sync(0xffffffffu, bk[r], off);
            float ok2 = __shfl_xor_sync(0xffffffffu, bk2[r], off);
            int   oi  = __shfl_xor_sync(0xffffffffu, bi[r], off);
            if (ok < bk[r]) { bk2[r] = fminf(bk[r], ok2); bk[r] = ok; bi[r] = oi; }
            else            { bk2[r] = fminf(bk2[r], ok); }
        }
        if (tig == 0) {
            int rin = warp_m * 32 + (r >> 1) * 16 + (r & 1) * 8 + g;
            mK[warp_n * 64 + rin]  = bk[r];
            mK2[warp_n * 64 + rin] = bk2[r];
            mI[warp_n * 64 + rin]  = bi[r];
        }
    }
    __syncthreads();
    if (tid < 64) {
        float B1 = 1e30f, B2 = 1e30f; int BI = 0;
#pragma unroll
        for (int n = 0; n < 4; n++) {
            float k1 = mK[n * 64 + tid], k2 = mK2[n * 64 + tid];
            int   ii = mI[n * 64 + tid];
            if (k1 < B1) { B2 = fminf(B1, k2); B1 = k1; BI = ii; }
            else         { B2 = fminf(B2, k1); }
        }
        int row = rowBase + tid;
        g_best[row] = BI;
        g_bestkey[row] = B1;
        if (B2 - B1 < THRESH) {
            g_packed[row] = ~0ull;
            int pos = atomicAdd(&g_count, 1);
            if (pos < LCAP) g_list[pos] = row;
        }
    }
}

// ---------------- verify1: per-row key consistency -> repair list ----------------
__global__ void verify1_kernel(const float* __restrict__ z, const float* __restrict__ cb) {
    int warp = threadIdx.x >> 5, lane = threadIdx.x & 31;
    int row = blockIdx.x * 8 + warp;
    int best = g_best[row];
    const float4* c4 = (const float4*)(cb + (size_t)best * DIM);
    const float4* z4 = (const float4*)(z + (size_t)row * DIM);
    float d = 0.f;
#pragma unroll
    for (int j = 0; j < 2; j++) {
        float4 a = z4[lane + 32 * j], b = c4[lane + 32 * j];
        d = fmaf(a.x, b.x, d); d = fmaf(a.y, b.y, d);
        d = fmaf(a.z, b.z, d); d = fmaf(a.w, b.w, d);
    }
#pragma unroll
    for (int off = 16; off; off >>= 1) d += __shfl_xor_sync(0xffffffffu, d, off);
    if (lane == 0) {
        float key = fmaf(-2.f, d, g_cbsq[best]);
        if (fabsf(key - g_bestkey[row]) > V1TOL) {
            g_packed[row] = ~0ull;
            int pos = atomicAdd(&g_count, 1);
            if (pos < LCAP) g_list[pos] = row;
        }
    }
}

// ---------------- exact rescore: one block per listed row, 4 shfl chains in flight ----------------
__device__ __forceinline__ unsigned long long pack_key(float k, int code) {
    unsigned u = __float_as_uint(k);
    u = (u & 0x80000000u) ? ~u : (u | 0x80000000u);
    return ((unsigned long long)u << 32) | (unsigned)code;
}

__global__ __launch_bounds__(256, 2) void rescore_kernel(
    const float* __restrict__ z, const float* __restrict__ cb) {
    __shared__ float zr[DIM];
    int count = g_count; if (count > LCAP) count = LCAP;
    int tid = threadIdx.x, wid = tid >> 5, lane = tid & 31;

    for (int li = blockIdx.x; li < count; li += gridDim.x) {
        int row = g_list[li];
        __syncthreads();
        for (int i = tid; i < DIM; i += 256) zr[i] = z[(size_t)row * DIM + i];
        __syncthreads();

        const float4* zz = (const float4*)(zr + lane * 8);
        float4 a0 = zz[0], a1 = zz[1];

        unsigned long long bestp = ~0ull;
        // warp covers codes [wid*256, wid*256+256), 4 independent shfl chains in flight
#pragma unroll
        for (int jo = 0; jo < 256; jo += 4) {
            float dd[4];
#pragma unroll
            for (int u = 0; u < 4; u++) {
                int code = wid * 256 + jo + u;
                const float4* c4 = (const float4*)(cb + (size_t)code * DIM + lane * 8);
                float4 b0 = __ldg(c4), b1 = __ldg(c4 + 1);
                float d0 = a0.x * b0.x + a0.y * b0.y;
                float d1 = a0.z * b0.z + a0.w * b0.w;
                d0 += a1.x * b1.x + a1.y * b1.y;
                d1 += a1.z * b1.z + a1.w * b1.w;
                dd[u] = d0 + d1;
            }
#pragma unroll
            for (int off = 16; off; off >>= 1)
#pragma unroll
                for (int u = 0; u < 4; u++)
                    dd[u] += __shfl_xor_sync(0xffffffffu, dd[u], off);
#pragma unroll
            for (int u = 0; u < 4; u++) {
                int code = wid * 256 + jo + u;
                float key = fmaf(-2.f, dd[u], __ldg(g_cbsq + code));
                unsigned long long p = pack_key(key, code);
                if (p < bestp) bestp = p;
            }
        }
        if (lane == 0) atomicMin(&g_packed[row], bestp);
    }
}

__global__ void fixup_kernel() {
    int count = g_count; if (count > LCAP) count = LCAP;
    for (int i = blockIdx.x * 256 + threadIdx.x; i < count; i += gridDim.x * 256) {
        int row = g_list[i];
        g_best[row] = (int)(g_packed[row] & 0xffffffffull);
    }
}

// ---------------- verify2: sampled exact argmin on repaired state (sets g_bad) ----------------
__global__ void verify2_kernel(const float* __restrict__ z, const float* __restrict__ cb) {
    __shared__ float zr[256];
    __shared__ float smin[256];
    __shared__ float sbk;
    int s = blockIdx.x, t = threadIdx.x;
    int row = s * 1024 + ((s * 37) & 127);
    int best = g_best[row];
    zr[t] = z[(size_t)row * DIM + t];
    if (t == 0) sbk = 1e30f;
    __syncthreads();
    const float4* z4 = (const float4*)zr;
    float m = 1e30f;
#pragma unroll 2
    for (int j = 0; j < 8; j++) {
        int code = t + j * 256;
        const float4* c4 = (const float4*)(cb + (size_t)code * DIM);
        float d = 0.f;
#pragma unroll 8
        for (int q = 0; q < 64; q++) {
            float4 a = z4[q], b = c4[q];
            d = fmaf(a.x, b.x, d); d = fmaf(a.y, b.y, d);
            d = fmaf(a.z, b.z, d); d = fmaf(a.w, b.w, d);
        }
        float key = fmaf(-2.f, d, g_cbsq[code]);
        m = fminf(m, key);
        if (code == best) sbk = key;
    }
    smin[t] = m;
    __syncthreads();
    for (int w = 128; w; w >>= 1) {
        if (t < w) smin[t] = fminf(smin[t], smin[t + w]);
        __syncthreads();
    }
    if (t == 0 && sbk > smin[0] + 0.04f) g_bad = 1;
}

// ---------------- fallback: exact FFMA argmin (catastrophe only) ----------------
#define FTM 64
#define FTN 64
#define FKC 32
#define FB_SMEM ((DIM*FTM + FTN*(FKC+1)) * (int)sizeof(float))

__global__ __launch_bounds__(256) void fallback_kernel(
    const float* __restrict__ z, const float* __restrict__ cb) {
    if (g_bad == 0) return;
    extern __shared__ float fsm[];
    float (*sZ)[FTM]      = (float (*)[FTM])fsm;
    float (*sC)[FKC + 1]  = (float (*)[FKC + 1])(fsm + DIM * FTM);

    const int tid = threadIdx.x;
    const int rowBase = blockIdx.x * FTM;

    for (int i = tid; i < FTM * DIM; i += 256) {
        int m = i >> 8, k = i & 255;
        sZ[k][m] = z[(size_t)(rowBase + m) * DIM + k];
    }

    const int cg = tid & 15;
    const int rg = tid >> 4;

    float bestKey[4] = {1e30f, 1e30f, 1e30f, 1e30f};
    int   bestIdx[4] = {0, 0, 0, 0};

    for (int ct = 0; ct < N_CODES; ct += FTN) {
        float acc[4][4];
#pragma unroll
        for (int a = 0; a < 4; a++)
#pragma unroll
            for (int b = 0; b < 4; b++) acc[a][b] = 0.f;

        for (int kc = 0; kc < DIM; kc += FKC) {
            __syncthreads();
            {
                int c = tid >> 5, kk = tid & 31;
#pragma unroll
                for (int j = 0; j < 8; j++)
                    sC[c + 8 * j][kk] = cb[(size_t)(ct + c + 8 * j) * DIM + kc + kk];
            }
            __syncthreads();

#pragma unroll 8
            for (int k = 0; k < FKC; k++) {
                float4 zv = *(const float4*)(&sZ[kc + k][rg * 4]);
                float c0 = sC[cg * 4 + 0][k];
                float c1 = sC[cg * 4 + 1][k];
                float c2 = sC[cg * 4 + 2][k];
                float c3 = sC[cg * 4 + 3][k];
                acc[0][0] += zv.x * c0; acc[0][1] += zv.x * c1; acc[0][2] += zv.x * c2; acc[0][3] += zv.x * c3;
                acc[1][0] += zv.y * c0; acc[1][1] += zv.y * c1; acc[1][2] += zv.y * c2; acc[1][3] += zv.y * c3;
                acc[2][0] += zv.z * c0; acc[2][1] += zv.z * c1; acc[2][2] += zv.z * c2; acc[2][3] += zv.z * c3;
                acc[3][0] += zv.w * c0; acc[3][1] += zv.w * c1; acc[3][2] += zv.w * c2; acc[3][3] += zv.w * c3;
            }
        }

#pragma unroll
        for (int ci = 0; ci < 4; ci++) {
            int code = ct + cg * 4 + ci;
            float csq = g_cbsq[code];
#pragma unroll
            for (int ri = 0; ri < 4; ri++) {
                float key = csq - 2.f * acc[ri][ci];
                if (key < bestKey[ri]) { bestKey[ri] = key; bestIdx[ri] = code; }
            }
        }
    }

#pragma unroll
    for (int ri = 0; ri < 4; ri++) {
        float k = bestKey[ri];
        int ix = bestIdx[ri];
#pragma unroll
        for (int off = 8; off; off >>= 1) {
            float k2 = __shfl_xor_sync(0xffffffffu, k, off);
            int   i2 = __shfl_xor_sync(0xffffffffu, ix, off);
            if (k2 < k || (k2 == k && i2 < ix)) { k = k2; ix = i2; }
        }
        if (cg == 0) g_best[rowBase + rg * 4 + ri] = ix;
    }
}

// ---------------- gather + losses ----------------
__global__ void gather_kernel(const float* __restrict__ z, const float* __restrict__ cb,
                              float* __restrict__ out_zq, float* __restrict__ out_idx,
                              int write_idx) {
    __shared__ float warp_s[8];
    int warp = threadIdx.x >> 5, lane = threadIdx.x & 31;
    int row = blockIdx.x * 8 + warp;
    int idx = g_best[row];

    const float4* src = (const float4*)(cb + (size_t)idx * DIM);
    const float4* zr  = (const float4*)(z + (size_t)row * DIM);
    float4*       dst = (float4*)(out_zq + (size_t)row * DIM);

    float s = 0.f;
#pragma unroll
    for (int j = 0; j < 2; j++) {
        int e = lane + 32 * j;
        float4 c = src[e];
        float4 v = zr[e];
        dst[e] = c;
        float dx = c.x - v.x, dy = c.y - v.y, dz = c.z - v.z, dw = c.w - v.w;
        s += dx * dx + dy * dy + dz * dz + dw * dw;
    }
#pragma unroll
    for (int off = 16; off; off >>= 1) s += __shfl_xor_sync(0xffffffffu, s, off);
    if (lane == 0) {
        warp_s[warp] = s;
        atomicAdd(&g_hist[idx], 1u);
        if (write_idx) out_idx[row] = (float)idx;
    }
    __syncthreads();
    if (threadIdx.x == 0) {
        float tt = 0.f;
#pragma unroll
        for (int w = 0; w < 8; w++) tt += warp_s[w];
        atomicAdd(&g_closs, (double)tt);
    }
}

__global__ void finalize_kernel(float* __restrict__ out_losses, int write_losses) {
    __shared__ double sh[256];
    int t = threadIdx.x;
    double e = 0.0;
    for (int c = t; c < N_CODES; c += 256) {
        float p = (float)g_hist[c] / (float)N_ROWS;
        e += (double)(p * logf(p + 1e-10f));
    }
    sh[t] = e;
    __syncthreads();
    for (int s = 128; s; s >>= 1) {
        if (t < s) sh[t] += sh[t + s];
        __syncthreads();
    }
    if (t == 0 && write_losses) {
        double entropy = -sh[0];
        float closs = (float)(g_closs / (double)((long long)N_ROWS * DIM));
        out_losses[0] = closs;
        out_losses[1] = logf((float)N_CODES) - (float)entropy;
    }
}

extern "C" void kernel_launch(void* const* d_in, const int* in_sizes, int n_in,
                              void* d_out, int out_size) {
    const float* z  = (const float*)d_in[0];
    const float* cb = (const float*)d_in[1];
    float* out = (float*)d_out;

    const long long ZQ = (long long)N_ROWS * DIM;
    int write_idx    = (long long)out_size >= ZQ + N_ROWS;
    int write_losses = (long long)out_size >= ZQ + N_ROWS + 2;

    cudaFuncSetAttribute(vq_mma_kernel,
                         cudaFuncAttributeMaxDynamicSharedMemorySize, SMEM_TOTAL);
    cudaFuncSetAttribute(fallback_kernel,
                         cudaFuncAttributeMaxDynamicSharedMemorySize, FB_SMEM);

    prep_kernel<<<N_CODES / 8, 256>>>(cb);
    vq_mma_kernel<<<N_ROWS / 64, NT, SMEM_TOTAL>>>(z);
    verify1_kernel<<<N_ROWS / 8, 256>>>(z, cb);
    rescore_kernel<<<2048, 256>>>(z, cb);
    fixup_kernel<<<64, 256>>>();
    verify2_kernel<<<64, 256>>>(z, cb);
    fallback_kernel<<<N_ROWS / FTM, 256, FB_SMEM>>>(z, cb);
    gather_kernel<<<N_ROWS / 8, 256>>>(z, cb, out, out + ZQ, write_idx);
    finalize_kernel<<<1, 256>>>(out + ZQ + N_ROWS, write_losses);
}